// round 10
// baseline (speedup 1.0000x reference)
#include <cuda_runtime.h>
#include <cstdint>

// ============================================================================
// 20-qubit depth-4 strongly-entangling circuit, batch 64, <Z_0>.
// 8 full-state sweeps, ping-pong A<->B; every pass READS a contiguous 64KB
// block per CTA, writes scattered 64B segments in the other buffer's layout.
//   buffer element (16B quad) = (Re_s0, Re_s1, Im_s0, Im_s1)  [ulonglong2:
//   .x = packed Re pair = X, .y = packed Im pair = Y]
//   buffer A (input of pass1): idx = r1*32768 + sg*4096 + c1*4 + s2
//   buffer B (input of pass2): idx = r2*32768 + sg*4096 + c2*4 + s2
// CNOT(19,0) folded into pass2's write base (even/odd d), CNOT(9,10) folded
// into pass2 W1 store offsets (d^15).  In-window CNOT chains folded statically
// into store indices (permk = prefix parity).  Rot: m11=conj(m00),
// m10=-conj(m01) -> 7 broadcast scalars, negations precomputed.
// All smem accesses are [base + compile-time-immediate]: the swizzle
// (idx ^ ((idx>>6&1)<<2)) is folded into per-window base pointers; in W3 a
// register relabel (reg k <-> cfg k^(u&1)) cancels it exactly.  Under that
// relabel, rot c0's |0>/|1> roles swap for u0=1 threads: the role-swapped
// matrix [[m11,m10],[m01,m00]] keeps the same conjugate structure
// (m00'=conj(m00), m01'=-conj(m01)) and is precomputed at table slot j=10.
// Streaming hints (__ldcs/__stcs).  2 __syncthreads per pass.
// ============================================================================

using u64 = unsigned long long;

#define NSTATE (1 << 20)

__device__ ulonglong2 g_A[(size_t)NSTATE * 32];      // 512 MB
__device__ ulonglong2 g_B[(size_t)NSTATE * 32];      // 512 MB
__device__ ulonglong2 g_rotB[4 * 2 * 11 * 4];        // j=0..9 rots, j=10 = swapped j=0
__device__ float2 g_cs[64 * 20];                     // (cos(x/2), sin(x/2)) per (s,w)

#define SGN 0x8000000080000000ULL

// ---------------- packed f32x2 helpers ----------------
__device__ __forceinline__ u64 f2mul(u64 a, u64 b) {
    u64 d; asm("mul.rn.f32x2 %0,%1,%2;" : "=l"(d) : "l"(a), "l"(b)); return d;
}
__device__ __forceinline__ u64 f2fma(u64 a, u64 b, u64 c) {
    u64 d; asm("fma.rn.f32x2 %0,%1,%2,%3;" : "=l"(d) : "l"(a), "l"(b), "l"(c)); return d;
}
__device__ __forceinline__ u64 f2add(u64 a, u64 b) {
    u64 d; asm("add.rn.f32x2 %0,%1,%2;" : "=l"(d) : "l"(a), "l"(b)); return d;
}
__device__ __forceinline__ u64 pk(float lo, float hi) {
    u64 d; asm("mov.b64 %0, {%1, %2};" : "=l"(d) : "f"(lo), "f"(hi)); return d;
}
__device__ __forceinline__ float2 up(u64 a) {
    float2 r; asm("mov.b64 {%0, %1}, %2;" : "=f"(r.x), "=f"(r.y) : "l"(a)); return r;
}
__device__ __forceinline__ u64 dupf(float v) {
    unsigned b = __float_as_uint(v); return (u64)b | ((u64)b << 32);
}

// ---------------- static CNOT-chain permutation (prefix parity) ----------------
// chain (k3,k2)(k2,k1)(k1,k0): d3=k3, d2=k2^k3, d1=k1^k2^k3, d0=k0^k1^k2^k3
__device__ __forceinline__ constexpr int permk(int k) {
    int p3 = (k >> 3) & 1;
    int p2 = ((k >> 2) & 1) ^ p3;
    int p1 = ((k >> 1) & 1) ^ p2;
    int p0 = (k & 1) ^ p1;
    return (p3 << 3) | (p2 << 2) | (p1 << 1) | p0;
}

// ---------------- Rot on 16-config register block ----------------
// m: {m00x, m00y, -m00y, m01x, -m01x, m01y, -m01y} broadcast in f32x2 pairs.
template <int Q>
__device__ __forceinline__ void rotg(u64* X, u64* Y, const u64* m) {
#pragma unroll
    for (int k = 0; k < 16; k++) {
        if (k & (1 << Q)) continue;
        const int k1 = k | (1 << Q);
        const u64 aX = X[k], aY = Y[k], bX = X[k1], bY = Y[k1];
        X[k]  = f2fma(m[6], bY, f2fma(m[3], bX, f2fma(m[2], aY, f2mul(m[0], aX))));
        Y[k]  = f2fma(m[5], bX, f2fma(m[3], bY, f2fma(m[1], aX, f2mul(m[0], aY))));
        X[k1] = f2fma(m[1], bY, f2fma(m[0], bX, f2fma(m[6], aY, f2mul(m[4], aX))));
        Y[k1] = f2fma(m[2], bX, f2fma(m[0], bY, f2fma(m[5], aX, f2mul(m[4], aY))));
    }
}

__device__ __forceinline__ void ldm(const ulonglong2* rmB, int j, u64* m) {
    const ulonglong2 q0 = rmB[j * 4 + 0], q1 = rmB[j * 4 + 1];
    const ulonglong2 q2 = rmB[j * 4 + 2], q3 = rmB[j * 4 + 3];
    m[0] = q0.x; m[1] = q0.y; m[2] = q1.x; m[3] = q1.y;
    m[4] = q2.x; m[5] = q2.y; m[6] = q3.x;
}

// ---------------- setup ----------------
__global__ void setup_kernel(const float* __restrict__ x,
                             const float* __restrict__ params) {
    int t = blockIdx.x * blockDim.x + threadIdx.x;
    if (t < 80) {
        // t = layer*20 + pass*10 + j ; wire = pass ? 19-j : 9-j
        int layer = t / 20, rest = t % 20, pass = rest / 10, j = rest % 10;
        int wire = pass ? (19 - j) : (9 - j);
        float phi = params[(layer * 20 + wire) * 3 + 0];
        float th  = params[(layer * 20 + wire) * 3 + 1];
        float om  = params[(layer * 20 + wire) * 3 + 2];
        float ct, st;  sincosf(0.5f * th, &st, &ct);
        float ap = -0.5f * (phi + om);
        float am =  0.5f * (phi - om);
        float ca, sa;  sincosf(ap, &sa, &ca);
        float cb, sb;  sincosf(am, &sb, &cb);
        // m00 = e^{i ap} ct ; m01 = -e^{i am} st ; m10 = -conj(m01) ; m11 = conj(m00)
        const float m00x = ca * ct, m00y = sa * ct;
        const float m01x = -cb * st, m01y = -sb * st;
        ulonglong2* blk = g_rotB + (layer * 2 + pass) * 44;
        ulonglong2 q;
        q.x = dupf(m00x); q.y = dupf(m00y);  blk[j * 4 + 0] = q;
        q.x = dupf(-m00y); q.y = dupf(m01x); blk[j * 4 + 1] = q;
        q.x = dupf(-m01x); q.y = dupf(m01y); blk[j * 4 + 2] = q;
        q.x = dupf(-m01y); q.y = 0;          blk[j * 4 + 3] = q;
        if (j == 0) {
            // Role-swapped variant for W3's relabeled rot c0 (u0=1 threads):
            // matrix [[m11,m10],[m01,m00]] -> m00'=(m00x,-m00y), m01'=(-m01x,m01y)
            q.x = dupf(m00x); q.y = dupf(-m00y);  blk[10 * 4 + 0] = q;
            q.x = dupf(m00y); q.y = dupf(-m01x);  blk[10 * 4 + 1] = q;
            q.x = dupf(m01x); q.y = dupf(m01y);   blk[10 * 4 + 2] = q;
            q.x = dupf(-m01y); q.y = 0;           blk[10 * 4 + 3] = q;
        }
    }
    int v = t - 80;
    if (v >= 0 && v < 64 * 20) {
        float c, s;  sincosf(0.5f * x[v], &s, &c);
        g_cs[v] = make_float2(c, s);
    }
}

__device__ __forceinline__ float2 rxf(float2 v, float2 f, int bit) {
    if (bit) return make_float2(f.y * v.y, -f.y * v.x);
    return make_float2(f.x * v.x, f.x * v.y);
}

// ---------------- main pass kernel ----------------
// PASS: 0 = pass1 (reads A, writes B), 1 = pass2 (reads B, writes A).
// MODE: 0 normal, 1 GEN (layer0 pass1, no read), 2 RED (layer3 pass2, no write).
template <int PASS, int MODE>
__global__ void __launch_bounds__(256, 2) qpass(int layer, float* __restrict__ out) {
    extern __shared__ ulonglong2 sm2[];          // 4096 x 16B = 64KB
    const int t  = threadIdx.x;
    const int s2 = t & 3;            // sample-pair id (2 packed samples)
    const int u  = t >> 2;           // 6 bits: complement of window's 4 k-bits
    const int u0 = u & 1;
    const int r  = blockIdx.x & 1023;
    const int sg = blockIdx.x >> 10;
    const ulonglong2* gin = (PASS == 0 ? g_A : g_B);
    ulonglong2* gout      = (PASS == 0 ? g_B : g_A);
    const ulonglong2* rmB = g_rotB + (layer * 2 + PASS) * 44;

    u64 X[16], Y[16];
    u64 m[7];

    // ================= Window 1 (k_q <-> c_{6+q}) =================
    if (MODE == 1) {
        // Generate post-RX product state directly (layer0 pass1).
        const float2* csA = g_cs + (sg * 8 + s2 * 2) * 20;
        const float2* csB = csA + 20;
        float2 a0 = make_float2(1.f, 0.f), a1 = make_float2(1.f, 0.f);
#pragma unroll
        for (int p = 0; p < 10; p++) {      // i bits 0..9 (= r), wire 19-p
            const int b = (r >> p) & 1;
            a0 = rxf(a0, csA[19 - p], b);
            a1 = rxf(a1, csB[19 - p], b);
        }
#pragma unroll
        for (int j = 0; j < 6; j++) {       // c bits 0..5 (= u), wire 9-j
            const int b = (u >> j) & 1;
            a0 = rxf(a0, csA[9 - j], b);
            a1 = rxf(a1, csB[9 - j], b);
        }
#pragma unroll
        for (int k = 0; k < 16; k++) {      // k_q -> wire 3-q
            float2 w0 = a0, w1 = a1;
#pragma unroll
            for (int q = 0; q < 4; q++) {
                const int b = (k >> q) & 1;
                w0 = rxf(w0, csA[3 - q], b);
                w1 = rxf(w1, csB[3 - q], b);
            }
            X[k] = pk(w0.x, w1.x);
            Y[k] = pk(w0.y, w1.y);
        }
    } else {
        // Dense contiguous read: CTA block = (r*8+sg)*64KB; per-k immediates.
        const ulonglong2* gi = gin + (size_t)(r * 8 + sg) * 4096 + ((u << 2) | s2);
#pragma unroll
        for (int k = 0; k < 16; k++) {
            const ulonglong2 v = __ldcs(gi + (k << 8));
            X[k] = v.x;
            Y[k] = v.y;
        }
    }
    // rots commute: Q0 first so FFMAs start after the first loads land.
    ldm(rmB, 6, m); rotg<0>(X, Y, m);       // rot c6
    ldm(rmB, 7, m); rotg<1>(X, Y, m);       // rot c7
    ldm(rmB, 8, m); rotg<2>(X, Y, m);       // rot c8
    ldm(rmB, 9, m); rotg<3>(X, Y, m);       // rot c9
    // W1 store: idx16 = (d<<8)|(u<<2)|s2, swizzle bit6 = u bit4 -> base fold.
    {
        ulonglong2* pW1 = sm2 + ((((u << 2) | s2)) ^ (((u >> 4) & 1) << 2));
        // pass2: CNOT(9,10) flips c9(k3) pre-chain -> chain-folded dest d^15.
        if (PASS == 1 && (r & 1)) {
#pragma unroll
            for (int k = 0; k < 16; k++) {
                ulonglong2 v; v.x = X[k]; v.y = Y[k];
                pW1[(permk(k) ^ 15) << 8] = v;   // CNOTs (c9,c8)(c8,c7)(c7,c6)
            }
        } else {
#pragma unroll
            for (int k = 0; k < 16; k++) {
                ulonglong2 v; v.x = X[k]; v.y = Y[k];
                pW1[permk(k) << 8] = v;
            }
        }
    }
    __syncthreads();

    // ================= Window 2 (k_q <-> c_{3+q}) =================
    // idx16 = ((u>>3)<<9)|(k<<5)|((u&7)<<2)|s2, swizzle bit6 = k bit1 ->
    // compile-time select between base and base^4.
    {
        const int bw2 = (((u >> 3) << 9) | ((u & 7) << 2) | s2);
        ulonglong2* pA = sm2 + bw2;
        ulonglong2* pB = sm2 + (bw2 ^ 4);
#pragma unroll
        for (int k = 0; k < 16; k++) {
            const ulonglong2 v = (((k >> 1) & 1) ? pB : pA)[k << 5];
            X[k] = v.x; Y[k] = v.y;
        }
        ldm(rmB, 3, m); rotg<0>(X, Y, m);   // rot c3
        ldm(rmB, 4, m); rotg<1>(X, Y, m);   // rot c4
        ldm(rmB, 5, m); rotg<2>(X, Y, m);   // rot c5
        // same per-thread address set as the load -> no barrier in between
#pragma unroll
        for (int k = 0; k < 16; k++) {
            const int d = permk(k);          // CNOTs (c6,c5)(c5,c4)(c4,c3)
            ulonglong2 v; v.x = X[k]; v.y = Y[k];
            (((d >> 1) & 1) ? pB : pA)[d << 5] = v;
        }
    }
    __syncthreads();

    // ================= Window 3 (k_q <-> c_q), reg relabel k <-> cfg k^u0 ====
    // idx16 = (u<<6)|(cfg<<2)|s2, swizzle bit6 = u bit0; with cfg = k^u0 the
    // swizzle cancels: addr = (u<<6)|s2 + (k<<2).  Register k holds cfg k^u0.
    {
        const ulonglong2* pW3 = sm2 + ((u << 6) | s2);
#pragma unroll
        for (int k = 0; k < 16; k++) {
            const ulonglong2 v = pW3[k << 2];
            X[k] = v.x; Y[k] = v.y;
        }
    }
    // rot c0 under the relabel: u0=1 threads need the role-swapped matrix
    // (precomputed at table slot j=10); u0=0 threads use the normal slot j=0.
    ldm(rmB, u0 ? 10 : 0, m); rotg<0>(X, Y, m);   // rot c0
    ldm(rmB, 1, m); rotg<1>(X, Y, m);             // rot c1
    ldm(rmB, 2, m); rotg<2>(X, Y, m);             // rot c2
    // CNOTs (c3,c2)(c2,c1)(c1,c0): dest cfg = permk(k^u0) = permk(k)^u0.

    if (MODE == 2) {
        // <Z_0> with final CNOT(19,0) folded: sign = bit19 ^ bit0.
        // bit19 = r bit 9 ; bit0 = dest cfg bit0 = (permk(k)^u0)&1.
        const int sbx = (((r >> 9) & 1) ^ u0);
        const u64 mA = sbx ? SGN : 0;        // mask when permk(k)&1 == 0
        const u64 mB = mA ^ SGN;             // mask when permk(k)&1 == 1
        u64 ps = 0;
#pragma unroll
        for (int k = 0; k < 16; k++) {
            u64 mag = f2fma(Y[k], Y[k], f2mul(X[k], X[k]));
            mag ^= (permk(k) & 1) ? mB : mA;
            ps = f2add(ps, mag);
        }
        ps = f2add(ps, __shfl_xor_sync(0xffffffffu, ps, 4));
        ps = f2add(ps, __shfl_xor_sync(0xffffffffu, ps, 8));
        ps = f2add(ps, __shfl_xor_sync(0xffffffffu, ps, 16));
        __syncthreads();                    // smem reuse barrier
        u64* smr = (u64*)sm2;
        const int lane = t & 31, wid = t >> 5;
        if (lane < 4) smr[wid * 4 + lane] = ps;
        __syncthreads();
        if (t < 4) {
            float2 acc = make_float2(0.f, 0.f);
#pragma unroll
            for (int w = 0; w < 8; w++) {
                const float2 q = up(smr[w * 4 + t]);
                acc.x += q.x; acc.y += q.y;
            }
            atomicAdd(out + sg * 8 + t * 2 + 0, acc.x);
            atomicAdd(out + sg * 8 + t * 2 + 1, acc.y);
        }
    } else {
        // Scatter-write into the other buffer's (next-pass-dense) layout.
        // global c = (u<<4)|(permk(k)^u0).  pass2 folds CNOT(19,0):
        // dest r bit9 ^= c bit0 -> even/odd-d base pointers.
        const size_t cb = (size_t)(u << 4) * 32768 + sg * 4096 + s2;
        ulonglong2* goE = gout + cb + r * 4;
        ulonglong2* goO = (PASS == 1) ? (gout + cb + (r ^ 512) * 4)
                                      : goE;
#pragma unroll
        for (int k = 0; k < 16; k++) {
            const int d = permk(k) ^ u0;     // runtime: 1 XOR (u0 per-thread)
            ulonglong2 v; v.x = X[k]; v.y = Y[k];
            __stcs(((d & 1) ? goO : goE) + d * 32768, v);
        }
    }
}

// ---------------------------------------------------------------------------
extern "C" void kernel_launch(void* const* d_in, const int* in_sizes, int n_in,
                              void* d_out, int out_size) {
    const float* x      = (const float*)d_in[0];
    const float* params = (const float*)d_in[1];
    if (n_in >= 2 && in_sizes[0] == 240 && in_sizes[1] == 1280) {  // defensive swap
        const float* tmp = x; x = params; params = tmp;
    }
    float* out = (float*)d_out;

    const size_t SH = 4096 * sizeof(ulonglong2);   // 64 KB dynamic smem
    cudaFuncSetAttribute(qpass<0, 1>, cudaFuncAttributeMaxDynamicSharedMemorySize, (int)SH);
    cudaFuncSetAttribute(qpass<0, 0>, cudaFuncAttributeMaxDynamicSharedMemorySize, (int)SH);
    cudaFuncSetAttribute(qpass<1, 0>, cudaFuncAttributeMaxDynamicSharedMemorySize, (int)SH);
    cudaFuncSetAttribute(qpass<1, 2>, cudaFuncAttributeMaxDynamicSharedMemorySize, (int)SH);

    setup_kernel<<<6, 256>>>(x, params);

    const int GRID = 8192, TB = 256;
    qpass<0, 1><<<GRID, TB, SH>>>(0, nullptr);   // layer0 pass1: GEN -> B
    qpass<1, 0><<<GRID, TB, SH>>>(0, nullptr);   // B -> A
    for (int d = 1; d <= 2; d++) {
        qpass<0, 0><<<GRID, TB, SH>>>(d, nullptr);   // A -> B
        qpass<1, 0><<<GRID, TB, SH>>>(d, nullptr);   // B -> A
    }
    qpass<0, 0><<<GRID, TB, SH>>>(3, nullptr);       // A -> B
    cudaMemsetAsync(d_out, 0, (size_t)out_size * sizeof(float));
    qpass<1, 2><<<GRID, TB, SH>>>(3, out);           // layer3 pass2: RED (reads B)
}